// round 13
// baseline (speedup 1.0000x reference)
#include <cuda_runtime.h>
#include <cuda_bf16.h>
#include <cstdint>

#define DD    128
#define NEV   4
#define NN    50000
#define EE    800000
#define ETOT  (EE + NN)
#define EPSF  1e-8f
#define NBLK  ((NN + 1023) / 1024)   // 49 scan blocks

// ---------------- device scratch (no allocations allowed) ----------------
// g_hb layout: node-major interleaved bf16 h[n][e][d] (row (n,e) = g_hb+(n*4+e)*128)
__device__ __nv_bfloat16 g_hb[(size_t)NEV * NN * DD];  // 51.2 MB
__device__ float    g_ssrc[NN * NEV];                  // interleaved [n][e]
__device__ float    g_sdst[NN * NEV];
__device__ unsigned g_max_enc[NEV];
// CSR build
__device__ int      g_cnt[NN];        // real-edge degree (self-loop added in scan)
__device__ int      g_rowptr[NN];
__device__ int      g_cursor[NN];
__device__ int      g_deg[NN];        // full degree incl self-loop
__device__ int      g_csrdst[ETOT];
__device__ int      g_bsum[NBLK + 1];
__device__ int      g_boff[NBLK + 1];

__device__ __forceinline__ unsigned enc_f(float f) {
    unsigned u = __float_as_uint(f);
    return (u & 0x80000000u) ? ~u : (u | 0x80000000u);
}
__device__ __forceinline__ float dec_u(unsigned u) {
    return (u & 0x80000000u) ? __uint_as_float(u ^ 0x80000000u)
                             : __uint_as_float(~u);
}
__device__ __forceinline__ float lrelu(float v) { return v > 0.f ? v : 0.01f * v; }
__device__ __forceinline__ uint32_t f2tf32(float f) {
    uint32_t u;
    asm("cvt.rna.tf32.f32 %0, %1;" : "=r"(u) : "f"(f));
    return u;
}

// ---------------- K0: zero counters --------------------------------------
__global__ void __launch_bounds__(256) k_zero() {
    int i = blockIdx.x * blockDim.x + threadIdx.x;
    if (i < NN) g_cnt[i] = 0;
    if (i < NEV) g_max_enc[i] = 0u;
}

// ---------------- K1: tf32 MMA GEMM + fused s epilogue, bf16 h store -----
__global__ void __launch_bounds__(256) k_gemm(const float* __restrict__ x,
                                              const float* __restrict__ w,
                                              const float* __restrict__ a) {
    __shared__ float As[128][36];
    __shared__ float Bs[32][136];
    __shared__ float s1_sm[128], s2_sm[128];
    __shared__ float a_sm[2][128];

    const int e   = blockIdx.y;
    const int n0  = blockIdx.x * 128;
    const int tid = threadIdx.x;
    const int lane = tid & 31, wid = tid >> 5;
    const int wm = wid & 3;
    const int wn = wid >> 2;
    const int qid = lane >> 2;
    const int qtr = lane & 3;

    if (tid < 128) {
        a_sm[0][tid] = a[e * 2 * DD + tid];
        a_sm[1][tid] = a[e * 2 * DD + DD + tid];
        s1_sm[tid] = 0.f;
        s2_sm[tid] = 0.f;
    }

    float c[2][8][4];
#pragma unroll
    for (int mi = 0; mi < 2; mi++)
#pragma unroll
        for (int ni = 0; ni < 8; ni++)
#pragma unroll
            for (int q = 0; q < 4; q++) c[mi][ni][q] = 0.f;

    const float* W = w + e * DD * DD;

    for (int k0 = 0; k0 < DD; k0 += 32) {
#pragma unroll
        for (int i = 0; i < 4; i++) {
            int idx = tid + i * 256;
            int row = idx >> 3, col4 = (idx & 7) << 2;
            float4 v = make_float4(0.f, 0.f, 0.f, 0.f);
            if (n0 + row < NN) v = *(const float4*)(x + (size_t)(n0 + row) * DD + k0 + col4);
            As[row][col4 + 0] = __uint_as_float(f2tf32(v.x));
            As[row][col4 + 1] = __uint_as_float(f2tf32(v.y));
            As[row][col4 + 2] = __uint_as_float(f2tf32(v.z));
            As[row][col4 + 3] = __uint_as_float(f2tf32(v.w));
        }
#pragma unroll
        for (int i = 0; i < 4; i++) {
            int idx = tid + i * 256;
            int kk = idx >> 5, c4 = (idx & 31) << 2;
            float4 v = *(const float4*)(W + (size_t)(k0 + kk) * DD + c4);
            Bs[kk][c4 + 0] = __uint_as_float(f2tf32(v.x));
            Bs[kk][c4 + 1] = __uint_as_float(f2tf32(v.y));
            Bs[kk][c4 + 2] = __uint_as_float(f2tf32(v.z));
            Bs[kk][c4 + 3] = __uint_as_float(f2tf32(v.w));
        }
        __syncthreads();

#pragma unroll
        for (int ks = 0; ks < 4; ks++) {
            const int kb = ks * 8;
            uint32_t af[2][4];
#pragma unroll
            for (int mi = 0; mi < 2; mi++) {
                int r = wm * 32 + mi * 16 + qid;
                af[mi][0] = __float_as_uint(As[r][kb + qtr]);
                af[mi][1] = __float_as_uint(As[r + 8][kb + qtr]);
                af[mi][2] = __float_as_uint(As[r][kb + qtr + 4]);
                af[mi][3] = __float_as_uint(As[r + 8][kb + qtr + 4]);
            }
            uint32_t bf[8][2];
#pragma unroll
            for (int ni = 0; ni < 8; ni++) {
                int ncol = wn * 64 + ni * 8 + qid;
                bf[ni][0] = __float_as_uint(Bs[kb + qtr][ncol]);
                bf[ni][1] = __float_as_uint(Bs[kb + qtr + 4][ncol]);
            }
#pragma unroll
            for (int mi = 0; mi < 2; mi++)
#pragma unroll
                for (int ni = 0; ni < 8; ni++)
                    asm volatile(
                        "mma.sync.aligned.m16n8k8.row.col.f32.tf32.tf32.f32 "
                        "{%0,%1,%2,%3}, {%4,%5,%6,%7}, {%8,%9}, {%0,%1,%2,%3};"
                        : "+f"(c[mi][ni][0]), "+f"(c[mi][ni][1]),
                          "+f"(c[mi][ni][2]), "+f"(c[mi][ni][3])
                        : "r"(af[mi][0]), "r"(af[mi][1]), "r"(af[mi][2]), "r"(af[mi][3]),
                          "r"(bf[ni][0]), "r"(bf[ni][1]));
        }
        __syncthreads();
    }

    // ---- epilogue: store bf16 h + fused s = h·a1 / h·a2 (from fp32 regs) ----
#pragma unroll
    for (int mi = 0; mi < 2; mi++) {
        int rA = wm * 32 + mi * 16 + qid;      // rows rA (c0,c1) and rA+8 (c2,c3)
        float s1a = 0.f, s2a = 0.f, s1b = 0.f, s2b = 0.f;
#pragma unroll
        for (int ni = 0; ni < 8; ni++) {
            int cb = wn * 64 + ni * 8 + 2 * qtr;
            float c0 = c[mi][ni][0], c1 = c[mi][ni][1];
            float c2 = c[mi][ni][2], c3 = c[mi][ni][3];
            if (n0 + rA < NN) {
                __nv_bfloat162 p = __float22bfloat162_rn(make_float2(c0, c1));
                *(__nv_bfloat162*)(g_hb + ((size_t)((n0 + rA) * NEV + e)) * DD + cb) = p;
            }
            if (n0 + rA + 8 < NN) {
                __nv_bfloat162 p = __float22bfloat162_rn(make_float2(c2, c3));
                *(__nv_bfloat162*)(g_hb + ((size_t)((n0 + rA + 8) * NEV + e)) * DD + cb) = p;
            }
            float a10 = a_sm[0][cb], a11 = a_sm[0][cb + 1];
            float a20 = a_sm[1][cb], a21 = a_sm[1][cb + 1];
            s1a += c0 * a10 + c1 * a11;
            s2a += c0 * a20 + c1 * a21;
            s1b += c2 * a10 + c3 * a11;
            s2b += c2 * a20 + c3 * a21;
        }
#pragma unroll
        for (int off = 1; off < 4; off <<= 1) {
            s1a += __shfl_xor_sync(0xffffffffu, s1a, off);
            s2a += __shfl_xor_sync(0xffffffffu, s2a, off);
            s1b += __shfl_xor_sync(0xffffffffu, s1b, off);
            s2b += __shfl_xor_sync(0xffffffffu, s2b, off);
        }
        if (qtr == 0) {
            atomicAdd(&s1_sm[rA], s1a);
            atomicAdd(&s2_sm[rA], s2a);
            atomicAdd(&s1_sm[rA + 8], s1b);
            atomicAdd(&s2_sm[rA + 8], s2b);
        }
    }
    __syncthreads();
    if (tid < 128 && n0 + tid < NN) {
        g_ssrc[(n0 + tid) * NEV + e] = s1_sm[tid];
        g_sdst[(n0 + tid) * NEV + e] = s2_sm[tid];
    }
}

// ---------------- K3: degree histogram (real edges only, int4 x4) --------
__global__ void __launch_bounds__(256) k_hist(const int* __restrict__ row) {
    int i = blockIdx.x * blockDim.x + threadIdx.x;
    if (i >= EE / 4) return;
    int4 r = ((const int4*)row)[i];
    atomicAdd(&g_cnt[r.x], 1);
    atomicAdd(&g_cnt[r.y], 1);
    atomicAdd(&g_cnt[r.z], 1);
    atomicAdd(&g_cnt[r.w], 1);
}

// ---------------- K4a: per-block exclusive scan (self-loop +1 folded) ----
__global__ void __launch_bounds__(1024) k_scan1() {
    int i = blockIdx.x * 1024 + threadIdx.x;
    int lane = threadIdx.x & 31, wid = threadIdx.x >> 5;
    int v = (i < NN) ? (g_cnt[i] + 1) : 0;   // +1 = self-loop
    if (i < NN) g_deg[i] = v;
    int s = v;
#pragma unroll
    for (int off = 1; off < 32; off <<= 1) {
        int t = __shfl_up_sync(0xffffffffu, s, off);
        if (lane >= off) s += t;
    }
    __shared__ int wsum[32];
    if (lane == 31) wsum[wid] = s;
    __syncthreads();
    if (wid == 0) {
        int t = wsum[lane];
        int sc = t;
#pragma unroll
        for (int off = 1; off < 32; off <<= 1) {
            int u = __shfl_up_sync(0xffffffffu, sc, off);
            if (lane >= off) sc += u;
        }
        wsum[lane] = sc - t;
    }
    __syncthreads();
    int excl = s - v + wsum[wid];
    if (i < NN) g_rowptr[i] = excl;
    if (threadIdx.x == 1023) g_bsum[blockIdx.x] = excl + v;
}

// ---------------- K4b: scan block sums -----------------------------------
__global__ void k_scan2() {
    if (threadIdx.x == 0) {
        int run = 0;
        for (int i = 0; i < NBLK; i++) {
            int t = g_bsum[i];
            g_boff[i] = run;
            run += t;
        }
    }
}

// ---------------- K4c: add block offsets, init cursors -------------------
__global__ void __launch_bounds__(1024) k_scan3() {
    int i = blockIdx.x * 1024 + threadIdx.x;
    if (i < NN) {
        int r = g_rowptr[i] + g_boff[i >> 10];
        g_rowptr[i] = r;
        g_cursor[i] = r;
    }
}

// ---------------- K5: CSR fill + per-env global max (fused, x2 edges) ----
__global__ void __launch_bounds__(256) k_fill_max(const int* __restrict__ row,
                                                  const int* __restrict__ col) {
    float m0 = -3.4e38f, m1 = -3.4e38f, m2 = -3.4e38f, m3 = -3.4e38f;
    const int NITEM = EE / 2 + NN;

    for (int k = blockIdx.x * blockDim.x + threadIdx.x; k < NITEM;
         k += gridDim.x * blockDim.x) {
        int s0, d0i, s1, d1i;
        bool two;
        if (k < EE / 2) {
            int2 r = ((const int2*)row)[k];
            int2 c = ((const int2*)col)[k];
            s0 = r.x; d0i = c.x; s1 = r.y; d1i = c.y;
            two = true;
        } else {
            s0 = d0i = k - EE / 2;
            s1 = d1i = 0;
            two = false;
        }
        {
            int slot = atomicAdd(&g_cursor[s0], 1);
            g_csrdst[slot] = d0i;
            float4 sa = ((const float4*)g_ssrc)[s0];
            float4 sb = ((const float4*)g_sdst)[d0i];
            m0 = fmaxf(m0, lrelu(sa.x + sb.x));
            m1 = fmaxf(m1, lrelu(sa.y + sb.y));
            m2 = fmaxf(m2, lrelu(sa.z + sb.z));
            m3 = fmaxf(m3, lrelu(sa.w + sb.w));
        }
        if (two) {
            int slot = atomicAdd(&g_cursor[s1], 1);
            g_csrdst[slot] = d1i;
            float4 sa = ((const float4*)g_ssrc)[s1];
            float4 sb = ((const float4*)g_sdst)[d1i];
            m0 = fmaxf(m0, lrelu(sa.x + sb.x));
            m1 = fmaxf(m1, lrelu(sa.y + sb.y));
            m2 = fmaxf(m2, lrelu(sa.z + sb.z));
            m3 = fmaxf(m3, lrelu(sa.w + sb.w));
        }
    }
    int lane = threadIdx.x & 31, wid = threadIdx.x >> 5;
#pragma unroll
    for (int off = 16; off > 0; off >>= 1) {
        m0 = fmaxf(m0, __shfl_xor_sync(0xffffffffu, m0, off));
        m1 = fmaxf(m1, __shfl_xor_sync(0xffffffffu, m1, off));
        m2 = fmaxf(m2, __shfl_xor_sync(0xffffffffu, m2, off));
        m3 = fmaxf(m3, __shfl_xor_sync(0xffffffffu, m3, off));
    }
    __shared__ float sm[8][NEV];
    if (lane == 0) { sm[wid][0] = m0; sm[wid][1] = m1; sm[wid][2] = m2; sm[wid][3] = m3; }
    __syncthreads();
    if (threadIdx.x < NEV) {
        int e = threadIdx.x;
        float mm = -3.4e38f;
#pragma unroll
        for (int wdx = 0; wdx < 8; wdx++) mm = fmaxf(mm, sm[wdx][e]);
        atomicMax(&g_max_enc[e], enc_f(mm));
    }
}

// ---------------- K7: agg, 1 warp per (node, env) ------------------------
// block = 128 threads = 4 warps = 1 node. Warp e accumulates env e only.
// Per-env accumulation order identical to prior version (j=0..deg-1).
__global__ void __launch_bounds__(128) k_agg(const float* __restrict__ x,
                                             const float* __restrict__ ew,
                                             float* __restrict__ out) {
    const int n    = blockIdx.x;
    const int e    = threadIdx.x >> 5;   // env = warp id
    const int lane = threadIdx.x & 31;
    __shared__ float4 red[3][32];

    const float ssrc = g_ssrc[n * NEV + e];
    const float M = dec_u(g_max_enc[e]);
    const int start = g_rowptr[n];
    const int deg   = g_deg[n];

    float4 acc = make_float4(0.f, 0.f, 0.f, 0.f);
    float den = 0.f;

#pragma unroll 4
    for (int j = 0; j < deg; j++) {
        int dst = __ldg(&g_csrdst[start + j]);
        float sd = __ldg(&g_sdst[dst * NEV + e]);
        float t = __expf(lrelu(ssrc + sd) - M);
        uint2 u = *(const uint2*)(g_hb + ((size_t)(dst * NEV + e)) * DD + lane * 4);
        float2 pa = __bfloat1622float2(*(__nv_bfloat162*)&u.x);
        float2 pb = __bfloat1622float2(*(__nv_bfloat162*)&u.y);
        acc.x += t * pa.x;
        acc.y += t * pa.y;
        acc.z += t * pb.x;
        acc.w += t * pb.y;
        den += t;
    }

    float wgt = ew[n * NEV + e] / (den + EPSF);
    float4 contrib = make_float4(wgt * acc.x, wgt * acc.y, wgt * acc.z, wgt * acc.w);
    if (e > 0) red[e - 1][lane] = contrib;
    __syncthreads();
    if (e == 0) {
        float4 o = ((const float4*)x)[n * 32 + lane];
        float4 r0 = red[0][lane], r1 = red[1][lane], r2 = red[2][lane];
        o.x += contrib.x + r0.x + r1.x + r2.x;
        o.y += contrib.y + r0.y + r1.y + r2.y;
        o.z += contrib.z + r0.z + r1.z + r2.z;
        o.w += contrib.w + r0.w + r1.w + r2.w;
        ((float4*)out)[n * 32 + lane] = o;
    }
}

// ---------------- launch --------------------------------------------------
extern "C" void kernel_launch(void* const* d_in, const int* in_sizes, int n_in,
                              void* d_out, int out_size) {
    const float* x   = (const float*)d_in[0];
    const int*   adj = (const int*)d_in[1];
    const float* ew  = (const float*)d_in[2];
    const float* w   = (const float*)d_in[3];
    const float* a   = (const float*)d_in[4];
    const int* row = adj;
    const int* col = adj + EE;
    float* out = (float*)d_out;

    k_zero<<<(NN + 255) / 256, 256>>>();

    dim3 g1((NN + 127) / 128, NEV);
    k_gemm<<<g1, 256>>>(x, w, a);

    k_hist<<<(EE / 4 + 255) / 256, 256>>>(row);
    k_scan1<<<NBLK, 1024>>>();
    k_scan2<<<1, 32>>>();
    k_scan3<<<NBLK, 1024>>>();

    k_fill_max<<<1024, 256>>>(row, col);

    k_agg<<<NN, 128>>>(x, ew, out);
}